// round 16
// baseline (speedup 1.0000x reference)
#include <cuda_runtime.h>
#include <math.h>
#include <stdint.h>

#define NPRED_TOTAL 259584      // 32 * 8112
#define NP0         8112        // predictions in batch 0 (3*52*52)
#define HW_         2704        // 52*52
#define ATTRS       85
#define OUT_ELEMS   22064640    // 32*8112*85
#define MAXDET      100
#define NCLS        80
#define CLS_CAP     512
#define MTX_CAP     256
#define MTX_W       8
#define KEPT_MAX    8192
#define NBUCK       4096        // (key>>32)&0xFFF : exp-LSB + 11 mantissa bits
#define POOL_CAP    1024
#define TOT_BLOCKS  (NPRED_TOTAL / 64)

// candidate record: 32B, written once by decode, read once by nms
struct __align__(16) Rec { float4 box; uint64_t key; uint64_t pad; };

// ---- device scratch ----
__device__ float4   g_corners[NP0];
__device__ float    g_conf[NP0];
__device__ float    g_clsconf[NP0];
__device__ float    g_clspred[NP0];
__device__ Rec      g_cls_rec[NCLS * CLS_CAP];
__device__ int      g_cls_cnt[NCLS];             // zero-init; reset per class block
__device__ uint64_t g_kept[KEPT_MAX];
__device__ int      g_kcount;
__device__ int      g_done;

// key (52 bits) = score_inv(32) << 20 | idx(13) << 7 | cls(7)

__device__ __forceinline__ float sigf(float x) { return 1.0f / (1.0f + expf(-x)); }

// ---------------------------------------------------------------------------
// Decode with inline candidate extraction (values already in smem — measured
// free in R8/R10). 64 preds per 256-thread block, quarter-split over attrs.
// ---------------------------------------------------------------------------
__global__ __launch_bounds__(256) void decode_kernel(
    const float* __restrict__ in,
    const float* __restrict__ anchors,
    float* __restrict__ out)
{
    __shared__ float sm[64 * ATTRS];
    const int tx = threadIdx.x;
    const int q  = tx >> 6;
    const int lp = tx & 63;
    const int n  = blockIdx.x * 64 + lp;
    const int b  = n / NP0;
    const int r  = n - b * NP0;
    const int a  = r / HW_;
    const int hw = r - a * HW_;
    const int gy = hw / 52;
    const int gx = hw - gy * 52;

    const float* p = in + ((long)(b * 255 + a * 85)) * HW_ + hw;
    float* row = sm + lp * ATTRS;

    float t[22];
    #pragma unroll
    for (int k = 0; k < 22; k++) {
        int e = q + 4 * k;
        if (e < ATTRS) t[k] = __ldcs(p + (long)e * HW_);
    }

    if (q == 0) {
        row[0] = (sigf(t[0]) + (float)gx) / 52.0f;
        row[4] = sigf(t[1]);
        #pragma unroll
        for (int k = 2; k < 22; k++) row[4 * k] = sigf(t[k]);
    } else if (q == 1) {
        row[1] = (sigf(t[0]) + (float)gy) / 52.0f;
        #pragma unroll
        for (int k = 1; k < 21; k++) row[1 + 4 * k] = sigf(t[k]);
    } else if (q == 2) {
        float aw = anchors[(6 + a) * 2 + 0] * 0.125f;
        row[2] = (expf(t[0]) * aw) / 52.0f;
        #pragma unroll
        for (int k = 1; k < 21; k++) row[2 + 4 * k] = sigf(t[k]);
    } else {
        float ah = anchors[(6 + a) * 2 + 1] * 0.125f;
        row[3] = (expf(t[0]) * ah) / 52.0f;
        #pragma unroll
        for (int k = 1; k < 21; k++) row[3 + 4 * k] = sigf(t[k]);
    }
    __syncthreads();

    // coalesced vectorized writeback
    {
        const float4* sm4 = (const float4*)sm;
        float4* ob4 = (float4*)(out + (long)blockIdx.x * (64 * ATTRS));
        #pragma unroll 6
        for (int i = tx; i < (64 * ATTRS) / 4; i += 256) __stcs(ob4 + i, sm4[i]);
    }

    // inline batch-0 candidate extraction from smem (blocks 0..126 only)
    if (tx < 64 && n < NP0) {
        float conf = row[4];
        float cc = row[5]; int cp = 0;
        #pragma unroll 16
        for (int c = 1; c < NCLS; c++) {
            float v = row[5 + c];
            if (v > cc) { cc = v; cp = c; }   // strict > : lowest idx on ties
        }
        float score = conf * cc;
        if (score >= 0.5f) {
            float bx = row[0], by = row[1], bw = row[2], bh = row[3];
            float hx = bw * 0.5f, hy = bh * 0.5f;
            float x1 = bx - hx, y1 = by - hy, x2 = bx + hx, y2 = by + hy;
            float off = (float)cp * 4096.0f;
            g_corners[n] = make_float4(x1, y1, x2, y2);
            g_conf[n]    = conf;
            g_clsconf[n] = cc;
            g_clspred[n] = (float)cp;
            uint64_t key = ((uint64_t)(__float_as_uint(score) ^ 0xFFFFFFFFu) << 20)
                         | ((uint64_t)(unsigned)n << 7) | (unsigned)cp;
            int pos = atomicAdd(&g_cls_cnt[cp], 1);
            if (pos < CLS_CAP) {
                Rec* rc = &g_cls_rec[cp * CLS_CAP + pos];
                rc->box = make_float4(x1 + off, y1 + off, x2 + off, y2 + off);
                rc->key = key;
            }
        }
    }
}

// ---------------------------------------------------------------------------
// Fused NMS: 80 blocks x 512 threads (uncontended now — runs after decode).
// One record-read hop, reg-resident rank-scatter (1 slot/thread), matrix
// fast path, last-block histogram top-100 merge.
// ---------------------------------------------------------------------------
__global__ __launch_bounds__(512) void nms_kernel(float* __restrict__ out)
{
    __shared__ __align__(16) char buf[24576];       // 24KB phase union
    uint64_t* s_key  = (uint64_t*)buf;              // [0,4K)  unsorted keys
    uint64_t* s_sort = (uint64_t*)(buf + 4096);     // [4K,8K) sorted keys
    float4*   s_box  = (float4*)(buf + 8192);       // [8K,16K) sorted boxes
    unsigned* s_thr  = (unsigned*)(buf + 16384);    // [16K,24K) threat matrix
    int*      s_hist = (int*)buf;                   // [0,16K)  (merge)
    uint64_t* s_pool = (uint64_t*)(buf + 16384);    // [16K,24K) (merge)

    __shared__ int s_kidx[MAXDET];
    __shared__ int s_ord[MAXDET];
    __shared__ int s_nk, s_gbase, s_ticket, s_bstar, s_pcnt;

    const int tid = threadIdx.x;
    const int c   = blockIdx.x;
    int nc = g_cls_cnt[c]; if (nc > CLS_CAP) nc = CLS_CAP;

    // load records: one slot per thread (nc <= 512)
    float4 rb = make_float4(0,0,0,0);
    uint64_t rk = 0;
    if (tid < nc) { Rec r = g_cls_rec[c * CLS_CAP + tid]; rb = r.box; rk = r.key; s_key[tid] = rk; }
    __syncthreads();

    // rank-scatter keys AND boxes through registers
    if (tid < nc) {
        int rnk = 0;
        for (int j = 0; j < nc; j++) rnk += (s_key[j] < rk) ? 1 : 0;
        s_sort[rnk] = rk; s_box[rnk] = rb;
    }
    __syncthreads();

    if (nc <= MTX_CAP) {
        if (tid < nc) {
            unsigned w[MTX_W];
            #pragma unroll
            for (int k = 0; k < MTX_W; k++) w[k] = 0u;
            float4 Q = s_box[tid];
            float aI = (Q.z - Q.x) * (Q.w - Q.y);
            for (int j = 0; j < tid; j++) {
                float4 P = s_box[j];
                float aJ = (P.z - P.x) * (P.w - P.y);
                float ltx = fmaxf(P.x, Q.x), lty = fmaxf(P.y, Q.y);
                float rbx = fminf(P.z, Q.z), rby = fminf(P.w, Q.w);
                float iw = fmaxf(rbx - ltx, 0.0f), ih = fmaxf(rby - lty, 0.0f);
                float inter = iw * ih;
                float den = aJ + aI - inter + 1e-9f;
                if (inter / den > 0.4f) w[j >> 5] |= 1u << (j & 31);
            }
            #pragma unroll
            for (int k = 0; k < MTX_W; k++) s_thr[tid * MTX_W + k] = w[k];
        }
        __syncthreads();

        if (tid < 32) {
            unsigned kw = 0u;
            int nk = 0;
            for (int i = 0; i < nc && nk < MAXDET; i++) {
                unsigned tw = (tid < MTX_W) ? (s_thr[i * MTX_W + tid] & kw) : 0u;
                if (__ballot_sync(0xffffffffu, tw != 0u) == 0u) {
                    if (tid == 0) s_kidx[nk] = i;
                    if (tid == (i >> 5)) kw |= 1u << (i & 31);
                    nk++;
                }
            }
            if (tid == 0) s_nk = nk;
        }
    } else {
        if (tid < 32) {
            const int lane = tid;
            int nk = 0;
            for (int i = 0; i < nc && nk < MAXDET; i++) {
                float4 B = s_box[i];
                float aC = (B.z - B.x) * (B.w - B.y);
                bool sup = false;
                #pragma unroll
                for (int t = 0; t < 4; t++) {
                    int idx = lane + (t << 5);
                    if (idx < nk) {
                        float4 K = s_box[s_kidx[idx]];
                        float aK = (K.z - K.x) * (K.w - K.y);
                        float ltx = fmaxf(K.x, B.x), lty = fmaxf(K.y, B.y);
                        float rbx = fminf(K.z, B.z), rby = fminf(K.w, B.w);
                        float iw = fmaxf(rbx - ltx, 0.0f), ih = fmaxf(rby - lty, 0.0f);
                        float inter = iw * ih;
                        float den = aK + aC - inter + 1e-9f;
                        if (inter / den > 0.4f) sup = true;
                    }
                }
                if (__ballot_sync(0xffffffffu, sup) == 0u) {
                    if (lane == 0) s_kidx[nk] = i;
                    nk++;
                    __syncwarp();
                }
            }
            if (lane == 0) s_nk = nk;
        }
    }
    __syncthreads();

    const int nk = s_nk;
    if (tid == 0) s_gbase = (nk > 0) ? atomicAdd(&g_kcount, nk) : 0;
    __syncthreads();
    for (int t = tid; t < nk; t += 512) {
        int gp = s_gbase + t;
        if (gp < KEPT_MAX) g_kept[gp] = s_sort[s_kidx[t]];
    }
    if (tid == 0) g_cls_cnt[c] = 0;

    __syncthreads();
    if (tid == 0) {
        __threadfence();
        s_ticket = atomicAdd(&g_done, 1);
    }
    __syncthreads();
    if (s_ticket != NCLS - 1) return;

    if (tid == 0) __threadfence();
    __syncthreads();

    // ===== last block: histogram top-100 merge =====
    int K = g_kcount; if (K > KEPT_MAX) K = KEPT_MAX;
    const int np = (K < MAXDET) ? K : MAXDET;

    for (int i = tid; i < NBUCK; i += 512) s_hist[i] = 0;
    if (tid == 0) { s_pcnt = 0; s_bstar = -1; }
    __syncthreads();

    for (int i = tid; i < K; i += 512)
        atomicAdd(&s_hist[(int)((g_kept[i] >> 32) & 0xFFFu)], 1);
    __syncthreads();

    if (tid < 32 && np > 0) {
        const int CH = NBUCK / 32;
        int sum = 0;
        for (int j = 0; j < CH; j++) sum += s_hist[tid * CH + j];
        int excl = sum;
        #pragma unroll
        for (int off = 1; off < 32; off <<= 1) {
            int v = __shfl_up_sync(0xffffffffu, excl, off);
            if ((int)tid >= off) excl += v;
        }
        excl -= sum;
        bool has = (excl < np) && (excl + sum >= np);
        unsigned bal = __ballot_sync(0xffffffffu, has);
        int src = __ffs(bal) - 1;
        if ((int)tid == src) {
            int run = excl;
            for (int j = 0; j < CH; j++) {
                run += s_hist[tid * CH + j];
                if (run >= np) { s_bstar = tid * CH + j; break; }
            }
        }
    }
    __syncthreads();

    const int bstar = s_bstar;
    for (int i = tid; i < K; i += 512) {
        uint64_t k = g_kept[i];
        if ((int)((k >> 32) & 0xFFFu) <= bstar) {
            int p = atomicAdd(&s_pcnt, 1);
            if (p < POOL_CAP) s_pool[p] = k;
        }
    }
    __syncthreads();

    int P = s_pcnt; if (P > POOL_CAP) P = POOL_CAP;
    for (int i = tid; i < P; i += 512) {
        uint64_t my = s_pool[i];
        int rnk = 0;
        for (int j = 0; j < P; j++) rnk += (s_pool[j] < my) ? 1 : 0;
        if (rnk < np) s_ord[rnk] = (int)((my >> 7) & 0x1FFFu);
    }
    __syncthreads();

    if (tid < MAXDET) {
        float* d = out + (long)OUT_ELEMS + tid * 7;
        if (tid < np) {
            int orig = s_ord[tid];
            float4 c4 = g_corners[orig];
            d[0] = c4.y * 416.0f;
            d[1] = c4.x * 416.0f;
            d[2] = c4.w * 416.0f;
            d[3] = c4.z * 416.0f;
            d[4] = g_conf[orig];
            d[5] = g_clsconf[orig];
            d[6] = g_clspred[orig];
        } else {
            #pragma unroll
            for (int e = 0; e < 7; e++) d[e] = 0.0f;
        }
    }

    if (tid == 0) { g_kcount = 0; g_done = 0; }
}

// ---------------------------------------------------------------------------
// Launch: single stream, two kernels. Extraction rides inside decode.
// ---------------------------------------------------------------------------
extern "C" void kernel_launch(void* const* d_in, const int* in_sizes, int n_in,
                              void* d_out, int out_size)
{
    const float* in      = (const float*)d_in[0];
    const float* anchors = (const float*)d_in[1];
    float* out = (float*)d_out;

    decode_kernel<<<TOT_BLOCKS, 256>>>(in, anchors, out);
    nms_kernel<<<NCLS, 512>>>(out);
}